// round 1
// baseline (speedup 1.0000x reference)
#include <cuda_runtime.h>
#include <cuda_bf16.h>
#include <math_constants.h>

#define BATCH 8
#define E 1024
#define HEADS 16
#define W 1024
#define DH 64

// ---------------------------------------------------------------------------
// Scratch (static __device__ arrays; no allocation anywhere)
// ---------------------------------------------------------------------------
__device__ float g_Q[(size_t)BATCH * E * W];                  // 32 MB
__device__ float g_K[(size_t)BATCH * E * W];                  // 32 MB
__device__ float g_V[(size_t)BATCH * E * W];                  // 32 MB
__device__ float g_S[(size_t)BATCH * HEADS * W * W];          // 512 MB  S/P [b,h,k,q]
__device__ float g_O[(size_t)BATCH * E * W];                  // 32 MB

// ---------------------------------------------------------------------------
// Generic batched SGEMM: C[b] = A(1024x1024) @ X[b](1024x1024) (+ bias)
// 128x128 tile, BK=16, 256 threads, 8x8 per thread.
// ---------------------------------------------------------------------------
__global__ __launch_bounds__(256) void gemm_AX(const float* __restrict__ A,
                                               const float* __restrict__ X,
                                               float* __restrict__ C,
                                               const float* __restrict__ bias)
{
    const int b  = blockIdx.z;
    const float* Xb = X + (size_t)b * E * W;
    float*       Cb = C + (size_t)b * E * W;
    const int m0 = blockIdx.y * 128;
    const int n0 = blockIdx.x * 128;

    __shared__ float As[16][128];
    __shared__ float Bs[16][128];

    const int t  = threadIdx.x;
    const int tx = t & 15;       // n sub-tile
    const int ty = t >> 4;       // m sub-tile

    float acc[8][8];
#pragma unroll
    for (int i = 0; i < 8; i++)
#pragma unroll
        for (int j = 0; j < 8; j++) acc[i][j] = 0.f;

    for (int k0 = 0; k0 < E; k0 += 16) {
        // A tile [128 m][16 k] -> As[k][m]
#pragma unroll
        for (int i = 0; i < 2; i++) {
            int slot = t + i * 256;          // 0..511
            int row  = slot >> 2;            // m 0..127
            int c4   = slot & 3;             // k group
            float4 v = *reinterpret_cast<const float4*>(&A[(size_t)(m0 + row) * E + k0 + c4 * 4]);
            As[c4 * 4 + 0][row] = v.x;
            As[c4 * 4 + 1][row] = v.y;
            As[c4 * 4 + 2][row] = v.z;
            As[c4 * 4 + 3][row] = v.w;
        }
        // X tile [16 k][128 n] -> Bs[k][n]
#pragma unroll
        for (int i = 0; i < 2; i++) {
            int slot = t + i * 256;
            int row  = slot >> 5;            // k 0..15
            int c4   = slot & 31;            // n group
            float4 v = *reinterpret_cast<const float4*>(&Xb[(size_t)(k0 + row) * W + n0 + c4 * 4]);
            *reinterpret_cast<float4*>(&Bs[row][c4 * 4]) = v;
        }
        __syncthreads();
#pragma unroll
        for (int kk = 0; kk < 16; kk++) {
            float ra[8], rb[8];
#pragma unroll
            for (int j = 0; j < 8; j++) ra[j] = As[kk][ty * 8 + j];
#pragma unroll
            for (int j = 0; j < 8; j++) rb[j] = Bs[kk][tx * 8 + j];
#pragma unroll
            for (int i = 0; i < 8; i++)
#pragma unroll
                for (int j = 0; j < 8; j++) acc[i][j] = fmaf(ra[i], rb[j], acc[i][j]);
        }
        __syncthreads();
    }

#pragma unroll
    for (int i = 0; i < 8; i++) {
        const int m = m0 + ty * 8 + i;
        const float bv = bias ? bias[m] : 0.f;
        float4 v0, v1;
        v0.x = acc[i][0] + bv; v0.y = acc[i][1] + bv; v0.z = acc[i][2] + bv; v0.w = acc[i][3] + bv;
        v1.x = acc[i][4] + bv; v1.y = acc[i][5] + bv; v1.z = acc[i][6] + bv; v1.w = acc[i][7] + bv;
        float* dst = &Cb[(size_t)m * W + n0 + tx * 8];
        *reinterpret_cast<float4*>(dst)     = v0;
        *reinterpret_cast<float4*>(dst + 4) = v1;
    }
}

// ---------------------------------------------------------------------------
// Transposed scores: S[b,h,k,q] = sum_d K[b,h,d,k] * Q[b,h,d,q]
// Fully masked tiles (q0 > k0+127) are skipped.
// ---------------------------------------------------------------------------
__global__ __launch_bounds__(256) void scores_kernel(const float* __restrict__ gK,
                                                     const float* __restrict__ gQ,
                                                     float* __restrict__ gS)
{
    const int bh = blockIdx.z;          // 0..127
    const int b  = bh >> 4;
    const int h  = bh & 15;
    const int k0 = blockIdx.y * 128;    // k tile (output row)
    const int q0 = blockIdx.x * 128;    // q tile (output col)
    if (q0 > k0 + 127) return;          // entirely above-diagonal -> masked, softmax never reads

    const float* Kb = gK + ((size_t)b * E + h * DH) * W;   // [64 d][W k], row stride W
    const float* Qb = gQ + ((size_t)b * E + h * DH) * W;
    float*       Sb = gS + (size_t)bh * W * W;

    __shared__ float Ks[16][128];   // [d][k]
    __shared__ float Qs[16][128];   // [d][q]

    const int t  = threadIdx.x;
    const int tx = t & 15;          // q
    const int ty = t >> 4;          // k

    float acc[8][8];
#pragma unroll
    for (int i = 0; i < 8; i++)
#pragma unroll
        for (int j = 0; j < 8; j++) acc[i][j] = 0.f;

    for (int d0 = 0; d0 < DH; d0 += 16) {
#pragma unroll
        for (int i = 0; i < 2; i++) {
            int slot = t + i * 256;
            int dd   = slot >> 5;       // 0..15
            int c4   = slot & 31;
            float4 vk = *reinterpret_cast<const float4*>(&Kb[(size_t)(d0 + dd) * W + k0 + c4 * 4]);
            *reinterpret_cast<float4*>(&Ks[dd][c4 * 4]) = vk;
            float4 vq = *reinterpret_cast<const float4*>(&Qb[(size_t)(d0 + dd) * W + q0 + c4 * 4]);
            *reinterpret_cast<float4*>(&Qs[dd][c4 * 4]) = vq;
        }
        __syncthreads();
#pragma unroll
        for (int dd = 0; dd < 16; dd++) {
            float ra[8], rb[8];
#pragma unroll
            for (int j = 0; j < 8; j++) ra[j] = Ks[dd][ty * 8 + j];
#pragma unroll
            for (int j = 0; j < 8; j++) rb[j] = Qs[dd][tx * 8 + j];
#pragma unroll
            for (int i = 0; i < 8; i++)
#pragma unroll
                for (int j = 0; j < 8; j++) acc[i][j] = fmaf(ra[i], rb[j], acc[i][j]);
        }
        __syncthreads();
    }

#pragma unroll
    for (int i = 0; i < 8; i++) {
        const int k = k0 + ty * 8 + i;
        float* dst = &Sb[(size_t)k * W + q0 + tx * 8];
        float4 v0, v1;
        v0.x = acc[i][0]; v0.y = acc[i][1]; v0.z = acc[i][2]; v0.w = acc[i][3];
        v1.x = acc[i][4]; v1.y = acc[i][5]; v1.z = acc[i][6]; v1.w = acc[i][7];
        *reinterpret_cast<float4*>(dst)     = v0;
        *reinterpret_cast<float4*>(dst + 4) = v1;
    }
}

// ---------------------------------------------------------------------------
// Row softmax over q for S[b,h,k, 0..k], scale E^-0.5 folded in.
// Writes the full W-length row (zeros for q > k) so the AV GEMM reads dense.
// ---------------------------------------------------------------------------
__global__ __launch_bounds__(256) void softmax_kernel(float* __restrict__ gS)
{
    const int k  = blockIdx.x;
    const int bh = blockIdx.y;
    float* row = gS + ((size_t)bh * W + k) * W;
    const int n = k + 1;                 // valid prefix length

    __shared__ float buf[W];
    __shared__ float red[256];
    const int t = threadIdx.x;

    float m = -CUDART_INF_F;
#pragma unroll
    for (int it = 0; it < W / 256; it++) {
        int q = t + it * 256;
        float v = (q < n) ? row[q] : -CUDART_INF_F;
        buf[q] = v;
        m = fmaxf(m, v);
    }
    red[t] = m;
    __syncthreads();
    for (int s = 128; s > 0; s >>= 1) {
        if (t < s) red[t] = fmaxf(red[t], red[t + s]);
        __syncthreads();
    }
    m = red[0];
    __syncthreads();

    float sum = 0.f;
#pragma unroll
    for (int it = 0; it < W / 256; it++) {
        int q = t + it * 256;
        float e = (q < n) ? __expf(buf[q] - m) : 0.f;
        buf[q] = e;
        sum += e;
    }
    red[t] = sum;
    __syncthreads();
    for (int s = 128; s > 0; s >>= 1) {
        if (t < s) red[t] += red[t + s];
        __syncthreads();
    }
    const float inv = 0.03125f / red[0];   // E^-0.5 = 1/32 folded into P

#pragma unroll
    for (int it = 0; it < W / 256; it++) {
        int q = t + it * 256;
        row[q] = buf[q] * inv;
    }
}

// ---------------------------------------------------------------------------
// O[b,h,d,k] = sum_q V[b,h,d,q] * P[b,h,k,q]   (q loop truncated at k0+128)
// 64(d) x 128(k) tile, BKq=16, 256 threads, 4x8 per thread.
// ---------------------------------------------------------------------------
__global__ __launch_bounds__(256) void av_kernel(const float* __restrict__ gV,
                                                 const float* __restrict__ gP,
                                                 float* __restrict__ gO)
{
    const int bh = blockIdx.y;
    const int b  = bh >> 4;
    const int h  = bh & 15;
    const int k0 = blockIdx.x * 128;

    const float* Vb = gV + ((size_t)b * E + h * DH) * W;
    const float* Pb = gP + (size_t)bh * W * W;
    float*       Ob = gO + ((size_t)b * E + h * DH) * W;

    __shared__ float Vs[16][65];    // [q][d], padded
    __shared__ float Ps[16][129];   // [q][k], padded

    const int t  = threadIdx.x;
    const int tx = t & 15;          // k: 8 each
    const int ty = t >> 4;          // d: 4 each

    float acc[4][8];
#pragma unroll
    for (int i = 0; i < 4; i++)
#pragma unroll
        for (int j = 0; j < 8; j++) acc[i][j] = 0.f;

    const int nq = k0 + 128;        // P is zero for q > k, so stop after diagonal tile
    for (int q0 = 0; q0 < nq; q0 += 16) {
        // V tile [64 d][16 q] -> Vs[q][d]
        {
            int dd = t >> 2, q4 = t & 3;
            float4 v = *reinterpret_cast<const float4*>(&Vb[(size_t)dd * W + q0 + q4 * 4]);
            Vs[q4 * 4 + 0][dd] = v.x;
            Vs[q4 * 4 + 1][dd] = v.y;
            Vs[q4 * 4 + 2][dd] = v.z;
            Vs[q4 * 4 + 3][dd] = v.w;
        }
        // P tile [128 k][16 q] -> Ps[q][k]
#pragma unroll
        for (int i = 0; i < 2; i++) {
            int slot = t + i * 256;
            int kr   = slot >> 2;
            int q4   = slot & 3;
            float4 p = *reinterpret_cast<const float4*>(&Pb[(size_t)(k0 + kr) * W + q0 + q4 * 4]);
            Ps[q4 * 4 + 0][kr] = p.x;
            Ps[q4 * 4 + 1][kr] = p.y;
            Ps[q4 * 4 + 2][kr] = p.z;
            Ps[q4 * 4 + 3][kr] = p.w;
        }
        __syncthreads();
#pragma unroll
        for (int qq = 0; qq < 16; qq++) {
            float rv[4], rp[8];
#pragma unroll
            for (int j = 0; j < 4; j++) rv[j] = Vs[qq][ty * 4 + j];
#pragma unroll
            for (int j = 0; j < 8; j++) rp[j] = Ps[qq][tx * 8 + j];
#pragma unroll
            for (int i = 0; i < 4; i++)
#pragma unroll
                for (int j = 0; j < 8; j++) acc[i][j] = fmaf(rv[i], rp[j], acc[i][j]);
        }
        __syncthreads();
    }

#pragma unroll
    for (int i = 0; i < 4; i++) {
        float* dst = &Ob[(size_t)(ty * 4 + i) * W + k0 + tx * 8];
        float4 v0, v1;
        v0.x = acc[i][0]; v0.y = acc[i][1]; v0.z = acc[i][2]; v0.w = acc[i][3];
        v1.x = acc[i][4]; v1.y = acc[i][5]; v1.z = acc[i][6]; v1.w = acc[i][7];
        *reinterpret_cast<float4*>(dst)     = v0;
        *reinterpret_cast<float4*>(dst + 4) = v1;
    }
}

// ---------------------------------------------------------------------------
// Launch
// ---------------------------------------------------------------------------
extern "C" void kernel_launch(void* const* d_in, const int* in_sizes, int n_in,
                              void* d_out, int out_size)
{
    const float* x  = (const float*)d_in[0];   // [3,B,E,W]: x[0]=K-in, x[1]=Q-in, x[2]=V-in
    const float* LQ = (const float*)d_in[1];
    const float* LK = (const float*)d_in[2];
    const float* LV = (const float*)d_in[3];
    const float* DM = (const float*)d_in[4];
    const float* Db = (const float*)d_in[5];
    float* out = (float*)d_out;

    float *pQ, *pK, *pV, *pS, *pO;
    cudaGetSymbolAddress((void**)&pQ, g_Q);
    cudaGetSymbolAddress((void**)&pK, g_K);
    cudaGetSymbolAddress((void**)&pV, g_V);
    cudaGetSymbolAddress((void**)&pS, g_S);
    cudaGetSymbolAddress((void**)&pO, g_O);

    const size_t BEW = (size_t)BATCH * E * W;

    dim3 gProj(W / 128, E / 128, BATCH);
    gemm_AX<<<gProj, 256>>>(LK, x + 0 * BEW, pK, nullptr);
    gemm_AX<<<gProj, 256>>>(LQ, x + 1 * BEW, pQ, nullptr);
    gemm_AX<<<gProj, 256>>>(LV, x + 2 * BEW, pV, nullptr);

    dim3 gSc(W / 128, W / 128, BATCH * HEADS);
    scores_kernel<<<gSc, 256>>>(pK, pQ, pS);

    dim3 gSm(W, BATCH * HEADS);
    softmax_kernel<<<gSm, 256>>>(pS);

    dim3 gAV(W / 128, BATCH * HEADS);
    av_kernel<<<gAV, 256>>>(pV, pS, pO);

    gemm_AX<<<gProj, 256>>>(DM, pO, out, Db);
}

// round 3
// speedup vs baseline: 1.6080x; 1.6080x over previous
#include <cuda_runtime.h>
#include <cuda_bf16.h>
#include <math_constants.h>
#include <cstdint>

#define BATCH 8
#define E 1024
#define HEADS 16
#define W 1024
#define DH 64

// ---------------------------------------------------------------------------
// Scratch (static __device__ arrays; no allocation anywhere)
// ---------------------------------------------------------------------------
__device__ float g_Q[(size_t)BATCH * E * W];
__device__ float g_K[(size_t)BATCH * E * W];
__device__ float g_V[(size_t)BATCH * E * W];
__device__ float g_S[(size_t)BATCH * HEADS * W * W];   // S/P [b,h,k,q]
__device__ float g_O[(size_t)BATCH * E * W];

__device__ __forceinline__ uint32_t smem_u32(const void* p) {
    uint32_t a;
    asm("{ .reg .u64 t; cvta.to.shared.u64 t, %1; cvt.u32.u64 %0, t; }" : "=r"(a) : "l"(p));
    return a;
}

__device__ __forceinline__ void ldsm_x4(uint32_t addr, uint32_t& r0, uint32_t& r1,
                                        uint32_t& r2, uint32_t& r3) {
    asm volatile("ldmatrix.sync.aligned.m8n8.x4.shared.b16 {%0,%1,%2,%3}, [%4];"
                 : "=r"(r0), "=r"(r1), "=r"(r2), "=r"(r3) : "r"(addr));
}
__device__ __forceinline__ void ldsm_x4_t(uint32_t addr, uint32_t& r0, uint32_t& r1,
                                          uint32_t& r2, uint32_t& r3) {
    asm volatile("ldmatrix.sync.aligned.m8n8.x4.trans.shared.b16 {%0,%1,%2,%3}, [%4];"
                 : "=r"(r0), "=r"(r1), "=r"(r2), "=r"(r3) : "r"(addr));
}
__device__ __forceinline__ void mma_bf16(float* c, const uint32_t* a, const uint32_t* b) {
    asm volatile("mma.sync.aligned.m16n8k16.row.col.f32.bf16.bf16.f32 "
                 "{%0,%1,%2,%3}, {%4,%5,%6,%7}, {%8,%9}, {%0,%1,%2,%3};"
                 : "+f"(c[0]), "+f"(c[1]), "+f"(c[2]), "+f"(c[3])
                 : "r"(a[0]), "r"(a[1]), "r"(a[2]), "r"(a[3]), "r"(b[0]), "r"(b[1]));
}

__device__ __forceinline__ void cvt_pack(float a, float b, uint32_t& hi, uint32_t& lo) {
    __nv_bfloat162 h = __floats2bfloat162_rn(a, b);
    float ra = a - __bfloat162float(h.x);
    float rb = b - __bfloat162float(h.y);
    __nv_bfloat162 l = __floats2bfloat162_rn(ra, rb);
    hi = *reinterpret_cast<uint32_t*>(&h);
    lo = *reinterpret_cast<uint32_t*>(&l);
}

// ---------------------------------------------------------------------------
// HMMA bf16x3 GEMM: C[b] = A(1024x1024) @ X[b](1024x1024) (+bias)
// CTA 128x128, BK=32, 8 warps (2x4), warp tile 64x32.
// A smem: [128 m][40 k] bf16 (pad 8)  -> row stride 80B (ldmatrix conflict-free)
// B smem: [32 k][136 n] bf16 (pad 8)  -> row stride 272B (ldmatrix conflict-free)
// ---------------------------------------------------------------------------
#define APAD 40
#define BPAD 136

__global__ __launch_bounds__(256, 2) void gemm_tc(const float* __restrict__ A,
                                                  const float* __restrict__ X,
                                                  float* __restrict__ C,
                                                  const float* __restrict__ bias)
{
    __shared__ __nv_bfloat16 As_hi[128 * APAD];
    __shared__ __nv_bfloat16 As_lo[128 * APAD];
    __shared__ __nv_bfloat16 Bs_hi[32 * BPAD];
    __shared__ __nv_bfloat16 Bs_lo[32 * BPAD];

    const int t    = threadIdx.x;
    const int wid  = t >> 5;
    const int lane = t & 31;
    const int wm   = wid & 1;          // 2 warps over M
    const int wn   = wid >> 1;         // 4 warps over N
    const int b    = blockIdx.z;
    const int m0   = blockIdx.y * 128;
    const int n0   = blockIdx.x * 128;
    const float* Xb = X + (size_t)b * E * W;
    float*       Cb = C + (size_t)b * E * W;

    const uint32_t sAhi = smem_u32(As_hi);
    const uint32_t sAlo = smem_u32(As_lo);
    const uint32_t sBhi = smem_u32(Bs_hi);
    const uint32_t sBlo = smem_u32(Bs_lo);

    // ldmatrix per-lane address components
    const int a_row = (lane & 7) + ((lane >> 3) & 1) * 8;   // 0..15
    const int a_k   = ((lane >> 4) & 1) * 8;                // 0 or 8
    const int b_k   = (lane & 7) + ((lane >> 3) & 1) * 8;   // 0..15
    const int b_n   = ((lane >> 4) & 1) * 8;                // 0 or 8

    float acc[4][4][4];
#pragma unroll
    for (int i = 0; i < 4; i++)
#pragma unroll
        for (int j = 0; j < 4; j++)
#pragma unroll
            for (int r = 0; r < 4; r++) acc[i][j][r] = 0.f;

    for (int c = 0; c < E / 32; c++) {
        const int kc = c * 32;
        // ---- A tile: 128x32 fp32 -> hi/lo bf16 ----
#pragma unroll
        for (int it = 0; it < 4; it++) {
            int idx = it * 256 + t;            // 0..1023 float4s
            int row = idx >> 3;                // 0..127
            int kq  = idx & 7;                 // 0..7
            float4 v = *reinterpret_cast<const float4*>(&A[(size_t)(m0 + row) * E + kc + kq * 4]);
            uint32_t h01, l01, h23, l23;
            cvt_pack(v.x, v.y, h01, l01);
            cvt_pack(v.z, v.w, h23, l23);
            uint2 hv = make_uint2(h01, h23);
            uint2 lv = make_uint2(l01, l23);
            *reinterpret_cast<uint2*>(&As_hi[row * APAD + kq * 4]) = hv;
            *reinterpret_cast<uint2*>(&As_lo[row * APAD + kq * 4]) = lv;
        }
        // ---- B tile: X[kc..kc+31][n0..n0+127] -> [k][n] hi/lo bf16 ----
#pragma unroll
        for (int it = 0; it < 4; it++) {
            int idx = it * 256 + t;            // 0..1023 float4s
            int kr  = idx >> 5;                // 0..31
            int nq  = idx & 31;                // 0..31
            float4 v = *reinterpret_cast<const float4*>(&Xb[(size_t)(kc + kr) * W + n0 + nq * 4]);
            uint32_t h01, l01, h23, l23;
            cvt_pack(v.x, v.y, h01, l01);
            cvt_pack(v.z, v.w, h23, l23);
            uint2 hv = make_uint2(h01, h23);
            uint2 lv = make_uint2(l01, l23);
            *reinterpret_cast<uint2*>(&Bs_hi[kr * BPAD + nq * 4]) = hv;
            *reinterpret_cast<uint2*>(&Bs_lo[kr * BPAD + nq * 4]) = lv;
        }
        __syncthreads();

        // ---- three split passes: hi*hi, hi*lo, lo*hi ----
#pragma unroll
        for (int pass = 0; pass < 3; pass++) {
            const uint32_t sA = (pass == 2) ? sAlo : sAhi;
            const uint32_t sB = (pass == 1) ? sBlo : sBhi;
#pragma unroll
            for (int s = 0; s < 2; s++) {      // k-steps of 16
                uint32_t a[4][4];
#pragma unroll
                for (int i = 0; i < 4; i++) {
                    uint32_t addr = sA + ((wm * 64 + i * 16 + a_row) * APAD + (s * 16 + a_k)) * 2;
                    ldsm_x4(addr, a[i][0], a[i][1], a[i][2], a[i][3]);
                }
                uint32_t bb[4][2];
#pragma unroll
                for (int j = 0; j < 2; j++) {  // pairs of n-frags
                    uint32_t addr = sB + ((s * 16 + b_k) * BPAD + (wn * 32 + j * 16 + b_n)) * 2;
                    uint32_t r0, r1, r2, r3;
                    ldsm_x4_t(addr, r0, r1, r2, r3);
                    bb[j * 2 + 0][0] = r0; bb[j * 2 + 0][1] = r1;
                    bb[j * 2 + 1][0] = r2; bb[j * 2 + 1][1] = r3;
                }
#pragma unroll
                for (int i = 0; i < 4; i++)
#pragma unroll
                    for (int j = 0; j < 4; j++)
                        mma_bf16(acc[i][j], a[i], bb[j]);
            }
        }
        __syncthreads();
    }

    // ---- epilogue ----
    const int gid  = lane >> 2;
    const int tid4 = lane & 3;
#pragma unroll
    for (int i = 0; i < 4; i++) {
        const int r0 = m0 + wm * 64 + i * 16 + gid;
        const int r1 = r0 + 8;
        const float bv0 = bias ? bias[r0] : 0.f;
        const float bv1 = bias ? bias[r1] : 0.f;
#pragma unroll
        for (int j = 0; j < 4; j++) {
            const int cc = n0 + wn * 32 + j * 8 + tid4 * 2;
            float2 v0 = make_float2(acc[i][j][0] + bv0, acc[i][j][1] + bv0);
            float2 v1 = make_float2(acc[i][j][2] + bv1, acc[i][j][3] + bv1);
            *reinterpret_cast<float2*>(&Cb[(size_t)r0 * W + cc]) = v0;
            *reinterpret_cast<float2*>(&Cb[(size_t)r1 * W + cc]) = v1;
        }
    }
}

// ---------------------------------------------------------------------------
// Transposed scores: S[b,h,k,q] = sum_d K[b,h,d,k] * Q[b,h,d,q]  (FFMA)
// ---------------------------------------------------------------------------
__global__ __launch_bounds__(256) void scores_kernel(const float* __restrict__ gK,
                                                     const float* __restrict__ gQ,
                                                     float* __restrict__ gS)
{
    const int bh = blockIdx.z;
    const int b  = bh >> 4;
    const int h  = bh & 15;
    const int k0 = blockIdx.y * 128;
    const int q0 = blockIdx.x * 128;
    if (q0 > k0 + 127) return;

    const float* Kb = gK + ((size_t)b * E + h * DH) * W;
    const float* Qb = gQ + ((size_t)b * E + h * DH) * W;
    float*       Sb = gS + (size_t)bh * W * W;

    __shared__ float Ks[16][128];
    __shared__ float Qs[16][128];

    const int t  = threadIdx.x;
    const int tx = t & 15;
    const int ty = t >> 4;

    float acc[8][8];
#pragma unroll
    for (int i = 0; i < 8; i++)
#pragma unroll
        for (int j = 0; j < 8; j++) acc[i][j] = 0.f;

    for (int d0 = 0; d0 < DH; d0 += 16) {
#pragma unroll
        for (int i = 0; i < 2; i++) {
            int slot = t + i * 256;
            int dd   = slot >> 5;
            int c4   = slot & 31;
            float4 vk = *reinterpret_cast<const float4*>(&Kb[(size_t)(d0 + dd) * W + k0 + c4 * 4]);
            *reinterpret_cast<float4*>(&Ks[dd][c4 * 4]) = vk;
            float4 vq = *reinterpret_cast<const float4*>(&Qb[(size_t)(d0 + dd) * W + q0 + c4 * 4]);
            *reinterpret_cast<float4*>(&Qs[dd][c4 * 4]) = vq;
        }
        __syncthreads();
#pragma unroll
        for (int dd = 0; dd < 16; dd++) {
            float ra[8], rb[8];
#pragma unroll
            for (int j = 0; j < 8; j++) ra[j] = Ks[dd][ty * 8 + j];
#pragma unroll
            for (int j = 0; j < 8; j++) rb[j] = Qs[dd][tx * 8 + j];
#pragma unroll
            for (int i = 0; i < 8; i++)
#pragma unroll
                for (int j = 0; j < 8; j++) acc[i][j] = fmaf(ra[i], rb[j], acc[i][j]);
        }
        __syncthreads();
    }

#pragma unroll
    for (int i = 0; i < 8; i++) {
        const int k = k0 + ty * 8 + i;
        float* dst = &Sb[(size_t)k * W + q0 + tx * 8];
        float4 v0, v1;
        v0.x = acc[i][0]; v0.y = acc[i][1]; v0.z = acc[i][2]; v0.w = acc[i][3];
        v1.x = acc[i][4]; v1.y = acc[i][5]; v1.z = acc[i][6]; v1.w = acc[i][7];
        *reinterpret_cast<float4*>(dst)     = v0;
        *reinterpret_cast<float4*>(dst + 4) = v1;
    }
}

// ---------------------------------------------------------------------------
// Row softmax over q for S[b,h,k, 0..k], scale E^-0.5 folded in.
// ---------------------------------------------------------------------------
__global__ __launch_bounds__(256) void softmax_kernel(float* __restrict__ gS)
{
    const int k  = blockIdx.x;
    const int bh = blockIdx.y;
    float* row = gS + ((size_t)bh * W + k) * W;
    const int n = k + 1;

    __shared__ float buf[W];
    __shared__ float red[256];
    const int t = threadIdx.x;

    float m = -CUDART_INF_F;
#pragma unroll
    for (int it = 0; it < W / 256; it++) {
        int q = t + it * 256;
        float v = (q < n) ? row[q] : -CUDART_INF_F;
        buf[q] = v;
        m = fmaxf(m, v);
    }
    red[t] = m;
    __syncthreads();
    for (int s = 128; s > 0; s >>= 1) {
        if (t < s) red[t] = fmaxf(red[t], red[t + s]);
        __syncthreads();
    }
    m = red[0];
    __syncthreads();

    float sum = 0.f;
#pragma unroll
    for (int it = 0; it < W / 256; it++) {
        int q = t + it * 256;
        float e = (q < n) ? __expf(buf[q] - m) : 0.f;
        buf[q] = e;
        sum += e;
    }
    red[t] = sum;
    __syncthreads();
    for (int s = 128; s > 0; s >>= 1) {
        if (t < s) red[t] += red[t + s];
        __syncthreads();
    }
    const float inv = 0.03125f / red[0];

#pragma unroll
    for (int it = 0; it < W / 256; it++) {
        int q = t + it * 256;
        row[q] = buf[q] * inv;
    }
}

// ---------------------------------------------------------------------------
// O[b,h,d,k] = sum_q V[b,h,d,q] * P[b,h,k,q]   (q loop truncated at k0+128)
// ---------------------------------------------------------------------------
__global__ __launch_bounds__(256) void av_kernel(const float* __restrict__ gV,
                                                 const float* __restrict__ gP,
                                                 float* __restrict__ gO)
{
    const int bh = blockIdx.y;
    const int b  = bh >> 4;
    const int h  = bh & 15;
    const int k0 = blockIdx.x * 128;

    const float* Vb = gV + ((size_t)b * E + h * DH) * W;
    const float* Pb = gP + (size_t)bh * W * W;
    float*       Ob = gO + ((size_t)b * E + h * DH) * W;

    __shared__ float Vs[16][65];
    __shared__ float Ps[16][129];

    const int t  = threadIdx.x;
    const int tx = t & 15;
    const int ty = t >> 4;

    float acc[4][8];
#pragma unroll
    for (int i = 0; i < 4; i++)
#pragma unroll
        for (int j = 0; j < 8; j++) acc[i][j] = 0.f;

    const int nq = k0 + 128;
    for (int q0 = 0; q0 < nq; q0 += 16) {
        {
            int dd = t >> 2, q4 = t & 3;
            float4 v = *reinterpret_cast<const float4*>(&Vb[(size_t)dd * W + q0 + q4 * 4]);
            Vs[q4 * 4 + 0][dd] = v.x;
            Vs[q4 * 4 + 1][dd] = v.y;
            Vs[q4 * 4 + 2][dd] = v.z;
            Vs[q4 * 4 + 3][dd] = v.w;
        }
#pragma unroll
        for (int i = 0; i < 2; i++) {
            int slot = t + i * 256;
            int kr   = slot >> 2;
            int q4   = slot & 3;
            float4 p = *reinterpret_cast<const float4*>(&Pb[(size_t)(k0 + kr) * W + q0 + q4 * 4]);
            Ps[q4 * 4 + 0][kr] = p.x;
            Ps[q4 * 4 + 1][kr] = p.y;
            Ps[q4 * 4 + 2][kr] = p.z;
            Ps[q4 * 4 + 3][kr] = p.w;
        }
        __syncthreads();
#pragma unroll
        for (int qq = 0; qq < 16; qq++) {
            float rv[4], rp[8];
#pragma unroll
            for (int j = 0; j < 4; j++) rv[j] = Vs[qq][ty * 4 + j];
#pragma unroll
            for (int j = 0; j < 8; j++) rp[j] = Ps[qq][tx * 8 + j];
#pragma unroll
            for (int i = 0; i < 4; i++)
#pragma unroll
                for (int j = 0; j < 8; j++) acc[i][j] = fmaf(rv[i], rp[j], acc[i][j]);
        }
        __syncthreads();
    }

#pragma unroll
    for (int i = 0; i < 4; i++) {
        float* dst = &Ob[(size_t)(ty * 4 + i) * W + k0 + tx * 8];
        float4 v0, v1;
        v0.x = acc[i][0]; v0.y = acc[i][1]; v0.z = acc[i][2]; v0.w = acc[i][3];
        v1.x = acc[i][4]; v1.y = acc[i][5]; v1.z = acc[i][6]; v1.w = acc[i][7];
        *reinterpret_cast<float4*>(dst)     = v0;
        *reinterpret_cast<float4*>(dst + 4) = v1;
    }
}

// ---------------------------------------------------------------------------
// Launch
// ---------------------------------------------------------------------------
extern "C" void kernel_launch(void* const* d_in, const int* in_sizes, int n_in,
                              void* d_out, int out_size)
{
    const float* x  = (const float*)d_in[0];
    const float* LQ = (const float*)d_in[1];
    const float* LK = (const float*)d_in[2];
    const float* LV = (const float*)d_in[3];
    const float* DM = (const float*)d_in[4];
    const float* Db = (const float*)d_in[5];
    float* out = (float*)d_out;

    float *pQ, *pK, *pV, *pS, *pO;
    cudaGetSymbolAddress((void**)&pQ, g_Q);
    cudaGetSymbolAddress((void**)&pK, g_K);
    cudaGetSymbolAddress((void**)&pV, g_V);
    cudaGetSymbolAddress((void**)&pS, g_S);
    cudaGetSymbolAddress((void**)&pO, g_O);

    const size_t BEW = (size_t)BATCH * E * W;

    dim3 gProj(W / 128, E / 128, BATCH);
    gemm_tc<<<gProj, 256>>>(LK, x + 0 * BEW, pK, nullptr);
    gemm_tc<<<gProj, 256>>>(LQ, x + 1 * BEW, pQ, nullptr);
    gemm_tc<<<gProj, 256>>>(LV, x + 2 * BEW, pV, nullptr);

    dim3 gSc(W / 128, W / 128, BATCH * HEADS);
    scores_kernel<<<gSc, 256>>>(pK, pQ, pS);

    dim3 gSm(W, BATCH * HEADS);
    softmax_kernel<<<gSm, 256>>>(pS);

    dim3 gAV(W / 128, BATCH * HEADS);
    av_kernel<<<gAV, 256>>>(pV, pS, pO);

    gemm_tc<<<gProj, 256>>>(DM, pO, out, Db);
}

// round 4
// speedup vs baseline: 3.1958x; 1.9874x over previous
#include <cuda_runtime.h>
#include <cuda_bf16.h>
#include <math_constants.h>
#include <cstdint>

#define BATCH 8
#define E 1024
#define HEADS 16
#define W 1024
#define DH 64

// ---------------------------------------------------------------------------
// Scratch (static __device__ arrays; no allocation anywhere)
// ---------------------------------------------------------------------------
__device__ float g_Q[(size_t)BATCH * E * W];
__device__ float g_K[(size_t)BATCH * E * W];
__device__ float g_V[(size_t)BATCH * E * W];
__device__ float g_O[(size_t)BATCH * E * W];

__device__ __forceinline__ uint32_t smem_u32(const void* p) {
    uint32_t a;
    asm("{ .reg .u64 t; cvta.to.shared.u64 t, %1; cvt.u32.u64 %0, t; }" : "=r"(a) : "l"(p));
    return a;
}

__device__ __forceinline__ void ldsm_x4(uint32_t addr, uint32_t& r0, uint32_t& r1,
                                        uint32_t& r2, uint32_t& r3) {
    asm volatile("ldmatrix.sync.aligned.m8n8.x4.shared.b16 {%0,%1,%2,%3}, [%4];"
                 : "=r"(r0), "=r"(r1), "=r"(r2), "=r"(r3) : "r"(addr));
}
__device__ __forceinline__ void ldsm_x4_t(uint32_t addr, uint32_t& r0, uint32_t& r1,
                                          uint32_t& r2, uint32_t& r3) {
    asm volatile("ldmatrix.sync.aligned.m8n8.x4.trans.shared.b16 {%0,%1,%2,%3}, [%4];"
                 : "=r"(r0), "=r"(r1), "=r"(r2), "=r"(r3) : "r"(addr));
}
__device__ __forceinline__ void mma_bf16(float* c, const uint32_t* a, const uint32_t* b) {
    asm volatile("mma.sync.aligned.m16n8k16.row.col.f32.bf16.bf16.f32 "
                 "{%0,%1,%2,%3}, {%4,%5,%6,%7}, {%8,%9}, {%0,%1,%2,%3};"
                 : "+f"(c[0]), "+f"(c[1]), "+f"(c[2]), "+f"(c[3])
                 : "r"(a[0]), "r"(a[1]), "r"(a[2]), "r"(a[3]), "r"(b[0]), "r"(b[1]));
}

__device__ __forceinline__ void cvt_pack(float a, float b, uint32_t& hi, uint32_t& lo) {
    __nv_bfloat162 h = __floats2bfloat162_rn(a, b);
    float ra = a - __bfloat162float(h.x);
    float rb = b - __bfloat162float(h.y);
    __nv_bfloat162 l = __floats2bfloat162_rn(ra, rb);
    hi = *reinterpret_cast<uint32_t*>(&h);
    lo = *reinterpret_cast<uint32_t*>(&l);
}
__device__ __forceinline__ __nv_bfloat16 bf_hi(float a) { return __float2bfloat16_rn(a); }

// ---------------------------------------------------------------------------
// HMMA bf16x3 GEMM: C[b] = A(1024x1024) @ X[b](1024x1024) (+bias)
// (unchanged from R3 — verified)
// ---------------------------------------------------------------------------
#define APAD 40
#define BPAD 136

__global__ __launch_bounds__(256, 2) void gemm_tc(const float* __restrict__ A,
                                                  const float* __restrict__ X,
                                                  float* __restrict__ C,
                                                  const float* __restrict__ bias)
{
    __shared__ __nv_bfloat16 As_hi[128 * APAD];
    __shared__ __nv_bfloat16 As_lo[128 * APAD];
    __shared__ __nv_bfloat16 Bs_hi[32 * BPAD];
    __shared__ __nv_bfloat16 Bs_lo[32 * BPAD];

    const int t    = threadIdx.x;
    const int wid  = t >> 5;
    const int lane = t & 31;
    const int wm   = wid & 1;
    const int wn   = wid >> 1;
    const int b    = blockIdx.z;
    const int m0   = blockIdx.y * 128;
    const int n0   = blockIdx.x * 128;
    const float* Xb = X + (size_t)b * E * W;
    float*       Cb = C + (size_t)b * E * W;

    const uint32_t sAhi = smem_u32(As_hi);
    const uint32_t sAlo = smem_u32(As_lo);
    const uint32_t sBhi = smem_u32(Bs_hi);
    const uint32_t sBlo = smem_u32(Bs_lo);

    const int a_row = (lane & 7) + ((lane >> 3) & 1) * 8;
    const int a_k   = ((lane >> 4) & 1) * 8;
    const int b_k   = (lane & 7) + ((lane >> 3) & 1) * 8;
    const int b_n   = ((lane >> 4) & 1) * 8;

    float acc[4][4][4];
#pragma unroll
    for (int i = 0; i < 4; i++)
#pragma unroll
        for (int j = 0; j < 4; j++)
#pragma unroll
            for (int r = 0; r < 4; r++) acc[i][j][r] = 0.f;

    for (int c = 0; c < E / 32; c++) {
        const int kc = c * 32;
#pragma unroll
        for (int it = 0; it < 4; it++) {
            int idx = it * 256 + t;
            int row = idx >> 3;
            int kq  = idx & 7;
            float4 v = *reinterpret_cast<const float4*>(&A[(size_t)(m0 + row) * E + kc + kq * 4]);
            uint32_t h01, l01, h23, l23;
            cvt_pack(v.x, v.y, h01, l01);
            cvt_pack(v.z, v.w, h23, l23);
            *reinterpret_cast<uint2*>(&As_hi[row * APAD + kq * 4]) = make_uint2(h01, h23);
            *reinterpret_cast<uint2*>(&As_lo[row * APAD + kq * 4]) = make_uint2(l01, l23);
        }
#pragma unroll
        for (int it = 0; it < 4; it++) {
            int idx = it * 256 + t;
            int kr  = idx >> 5;
            int nq  = idx & 31;
            float4 v = *reinterpret_cast<const float4*>(&Xb[(size_t)(kc + kr) * W + n0 + nq * 4]);
            uint32_t h01, l01, h23, l23;
            cvt_pack(v.x, v.y, h01, l01);
            cvt_pack(v.z, v.w, h23, l23);
            *reinterpret_cast<uint2*>(&Bs_hi[kr * BPAD + nq * 4]) = make_uint2(h01, h23);
            *reinterpret_cast<uint2*>(&Bs_lo[kr * BPAD + nq * 4]) = make_uint2(l01, l23);
        }
        __syncthreads();

#pragma unroll
        for (int pass = 0; pass < 3; pass++) {
            const uint32_t sA = (pass == 2) ? sAlo : sAhi;
            const uint32_t sB = (pass == 1) ? sBlo : sBhi;
#pragma unroll
            for (int s = 0; s < 2; s++) {
                uint32_t a[4][4];
#pragma unroll
                for (int i = 0; i < 4; i++) {
                    uint32_t addr = sA + ((wm * 64 + i * 16 + a_row) * APAD + (s * 16 + a_k)) * 2;
                    ldsm_x4(addr, a[i][0], a[i][1], a[i][2], a[i][3]);
                }
                uint32_t bb[4][2];
#pragma unroll
                for (int j = 0; j < 2; j++) {
                    uint32_t addr = sB + ((s * 16 + b_k) * BPAD + (wn * 32 + j * 16 + b_n)) * 2;
                    uint32_t r0, r1, r2, r3;
                    ldsm_x4_t(addr, r0, r1, r2, r3);
                    bb[j * 2 + 0][0] = r0; bb[j * 2 + 0][1] = r1;
                    bb[j * 2 + 1][0] = r2; bb[j * 2 + 1][1] = r3;
                }
#pragma unroll
                for (int i = 0; i < 4; i++)
#pragma unroll
                    for (int j = 0; j < 4; j++)
                        mma_bf16(acc[i][j], a[i], bb[j]);
            }
        }
        __syncthreads();
    }

    const int gid  = lane >> 2;
    const int tid4 = lane & 3;
#pragma unroll
    for (int i = 0; i < 4; i++) {
        const int r0 = m0 + wm * 64 + i * 16 + gid;
        const int r1 = r0 + 8;
        const float bv0 = bias ? bias[r0] : 0.f;
        const float bv1 = bias ? bias[r1] : 0.f;
#pragma unroll
        for (int j = 0; j < 4; j++) {
            const int cc = n0 + wn * 32 + j * 8 + tid4 * 2;
            *reinterpret_cast<float2*>(&Cb[(size_t)r0 * W + cc]) =
                make_float2(acc[i][j][0] + bv0, acc[i][j][1] + bv0);
            *reinterpret_cast<float2*>(&Cb[(size_t)r1 * W + cc]) =
                make_float2(acc[i][j][2] + bv1, acc[i][j][3] + bv1);
        }
    }
}

// ---------------------------------------------------------------------------
// Fused flash attention (transposed layout):
//   rows = k index, columns = q index.
//   S[k,q] = sum_d K[d,k]*Q[d,q]  (valid where q <= k)
//   P = softmax over q (per row), * E^-0.5
//   O[k,d] = sum_q P[k,q] * V[d,q]   -> stored to g_O as [d][k]
// CTA: one 128-row k-tile per (kt, bh). 8 warps, each owns 16 k-rows (FA2).
// bf16 hi/lo 3-pass split for both MMAs.
// ---------------------------------------------------------------------------
#define KPAD 72     // [k][d] tiles: d stride (64+8)
#define QPAD 136    // [d][q] tile : q stride (128+8)
// smem byte offsets
#define F_KTH 0
#define F_KTL (F_KTH + 128 * KPAD * 2)     // 18432
#define F_QSH (F_KTL + 128 * KPAD * 2)     // 36864
#define F_QSL (F_QSH + 64 * QPAD * 2)      // 54272
#define F_VSH (F_QSL + 64 * QPAD * 2)      // 71680
#define F_VSL (F_VSH + 128 * KPAD * 2)     // 90112
#define F_TOTAL (F_VSL + 128 * KPAD * 2)   // 108544
#define OSM_STRIDE 132                      // fp32 [64 d][132] overlay at offset 0

__global__ __launch_bounds__(256, 1) void flash_kernel(const float* __restrict__ gK,
                                                       const float* __restrict__ gQ,
                                                       const float* __restrict__ gV,
                                                       float* __restrict__ gO)
{
    extern __shared__ char sm[];
    __nv_bfloat16* KtH = reinterpret_cast<__nv_bfloat16*>(sm + F_KTH);
    __nv_bfloat16* KtL = reinterpret_cast<__nv_bfloat16*>(sm + F_KTL);
    __nv_bfloat16* QsH = reinterpret_cast<__nv_bfloat16*>(sm + F_QSH);
    __nv_bfloat16* QsL = reinterpret_cast<__nv_bfloat16*>(sm + F_QSL);
    __nv_bfloat16* VsH = reinterpret_cast<__nv_bfloat16*>(sm + F_VSH);
    __nv_bfloat16* VsL = reinterpret_cast<__nv_bfloat16*>(sm + F_VSL);

    const uint32_t sKtH = smem_u32(KtH), sKtL = smem_u32(KtL);
    const uint32_t sQsH = smem_u32(QsH), sQsL = smem_u32(QsL);
    const uint32_t sVsH = smem_u32(VsH), sVsL = smem_u32(VsL);

    const int t    = threadIdx.x;
    const int wid  = t >> 5;
    const int lane = t & 31;
    const int gid  = lane >> 2;
    const int tid4 = lane & 3;

    const int kt = gridDim.x - 1 - blockIdx.x;     // heavy tiles first
    const int k0 = kt * 128;
    const int bh = blockIdx.y;
    const float* Kb = gK + (size_t)bh * DH * W;
    const float* Qb = gQ + (size_t)bh * DH * W;
    const float* Vb = gV + (size_t)bh * DH * W;
    float*       Ob = gO + (size_t)bh * DH * W;

    const int a_row = (lane & 7) + ((lane >> 3) & 1) * 8;
    const int a_k   = ((lane >> 4) & 1) * 8;
    const int b_k   = a_row;
    const int b_n   = a_k;

    // ---- prologue: K tile [d][k0..] -> transposed smem [k][d] hi/lo ----
#pragma unroll
    for (int it = 0; it < 8; it++) {
        int i  = it * 256 + t;           // 0..2047
        int k  = i & 127;
        int dc = i >> 7;                 // 0..15
        int d0 = dc * 4;
        float v0 = Kb[(size_t)(d0 + 0) * W + k0 + k];
        float v1 = Kb[(size_t)(d0 + 1) * W + k0 + k];
        float v2 = Kb[(size_t)(d0 + 2) * W + k0 + k];
        float v3 = Kb[(size_t)(d0 + 3) * W + k0 + k];
        uint32_t h01, l01, h23, l23;
        cvt_pack(v0, v1, h01, l01);
        cvt_pack(v2, v3, h23, l23);
        *reinterpret_cast<uint2*>(&KtH[k * KPAD + d0]) = make_uint2(h01, h23);
        *reinterpret_cast<uint2*>(&KtL[k * KPAD + d0]) = make_uint2(l01, l23);
    }

    // running stats (two rows per thread: r0 = wid*16+gid, r1 = +8)
    float m0 = -1e30f, m1 = -1e30f;
    float l0 = 0.f, l1 = 0.f;
    float oacc[8][4];
#pragma unroll
    for (int n = 0; n < 8; n++)
#pragma unroll
        for (int r = 0; r < 4; r++) oacc[n][r] = 0.f;

    for (int qt = 0; qt <= kt; qt++) {
        const int q0 = qt * 128;
        __syncthreads();   // previous iteration's MMAs done before overwriting tiles

        // ---- Q tile: [d][q] straight copy, hi/lo ----
#pragma unroll
        for (int it = 0; it < 8; it++) {
            int i  = it * 256 + t;       // 0..2047 float4s
            int d  = i >> 5;
            int q4 = (i & 31) * 4;
            float4 v = *reinterpret_cast<const float4*>(&Qb[(size_t)d * W + q0 + q4]);
            uint32_t h01, l01, h23, l23;
            cvt_pack(v.x, v.y, h01, l01);
            cvt_pack(v.z, v.w, h23, l23);
            *reinterpret_cast<uint2*>(&QsH[d * QPAD + q4]) = make_uint2(h01, h23);
            *reinterpret_cast<uint2*>(&QsL[d * QPAD + q4]) = make_uint2(l01, l23);
        }
        // ---- V tile: [d][q] -> transposed smem [q][d] hi/lo ----
#pragma unroll
        for (int it = 0; it < 8; it++) {
            int i  = it * 256 + t;
            int q  = i & 127;
            int dc = i >> 7;
            int d0 = dc * 4;
            float v0 = Vb[(size_t)(d0 + 0) * W + q0 + q];
            float v1 = Vb[(size_t)(d0 + 1) * W + q0 + q];
            float v2 = Vb[(size_t)(d0 + 2) * W + q0 + q];
            float v3 = Vb[(size_t)(d0 + 3) * W + q0 + q];
            uint32_t h01, l01, h23, l23;
            cvt_pack(v0, v1, h01, l01);
            cvt_pack(v2, v3, h23, l23);
            *reinterpret_cast<uint2*>(&VsH[q * KPAD + d0]) = make_uint2(h01, h23);
            *reinterpret_cast<uint2*>(&VsL[q * KPAD + d0]) = make_uint2(l01, l23);
        }
        __syncthreads();

        // ---- S = K^T Q : m=16 rows (this warp), n=128 q, contract d=64 ----
        float sacc[16][4];
#pragma unroll
        for (int j = 0; j < 16; j++)
#pragma unroll
            for (int r = 0; r < 4; r++) sacc[j][r] = 0.f;

#pragma unroll
        for (int pass = 0; pass < 3; pass++) {
            const uint32_t sA = (pass == 2) ? sKtL : sKtH;
            const uint32_t sB = (pass == 1) ? sQsL : sQsH;
#pragma unroll
            for (int s = 0; s < 4; s++) {
                uint32_t a[4];
                ldsm_x4(sA + ((wid * 16 + a_row) * KPAD + s * 16 + a_k) * 2,
                        a[0], a[1], a[2], a[3]);
#pragma unroll
                for (int j = 0; j < 4; j++) {
                    uint32_t r0, r1, r2, r3;
                    ldsm_x4_t(sB + ((s * 16 + b_k) * QPAD + j * 32 + b_n) * 2,
                              r0, r1, r2, r3);
                    uint32_t bb0[2] = {r0, r1};
                    uint32_t bb1[2] = {r2, r3};
                    mma_bf16(sacc[j * 4 + 0], a, bb0);
                    mma_bf16(sacc[j * 4 + 1], a, bb1);
                    uint32_t r4, r5, r6, r7;
                    ldsm_x4_t(sB + ((s * 16 + b_k) * QPAD + j * 32 + 16 + b_n) * 2,
                              r4, r5, r6, r7);
                    uint32_t bb2[2] = {r4, r5};
                    uint32_t bb3[2] = {r6, r7};
                    mma_bf16(sacc[j * 4 + 2], a, bb2);
                    mma_bf16(sacc[j * 4 + 3], a, bb3);
                }
            }
        }

        // ---- causal mask on the diagonal tile: q > k -> -inf ----
        if (qt == kt) {
            const int r0 = wid * 16 + gid;
            const int r1 = r0 + 8;
#pragma unroll
            for (int j = 0; j < 16; j++) {
                int qb = j * 8 + tid4 * 2;
                if (qb     > r0) sacc[j][0] = -1e30f;
                if (qb + 1 > r0) sacc[j][1] = -1e30f;
                if (qb     > r1) sacc[j][2] = -1e30f;
                if (qb + 1 > r1) sacc[j][3] = -1e30f;
            }
        }

        // ---- online softmax over q (per row) ----
        float mx0 = -1e30f, mx1 = -1e30f;
#pragma unroll
        for (int j = 0; j < 16; j++) {
            mx0 = fmaxf(mx0, fmaxf(sacc[j][0], sacc[j][1]));
            mx1 = fmaxf(mx1, fmaxf(sacc[j][2], sacc[j][3]));
        }
        mx0 = fmaxf(mx0, __shfl_xor_sync(0xffffffff, mx0, 1));
        mx0 = fmaxf(mx0, __shfl_xor_sync(0xffffffff, mx0, 2));
        mx1 = fmaxf(mx1, __shfl_xor_sync(0xffffffff, mx1, 1));
        mx1 = fmaxf(mx1, __shfl_xor_sync(0xffffffff, mx1, 2));

        const float nm0 = fmaxf(m0, mx0);
        const float nm1 = fmaxf(m1, mx1);
        const float sc0 = __expf(m0 - nm0);
        const float sc1 = __expf(m1 - nm1);
        float sum0 = 0.f, sum1 = 0.f;
#pragma unroll
        for (int j = 0; j < 16; j++) {
            sacc[j][0] = __expf(sacc[j][0] - nm0);
            sacc[j][1] = __expf(sacc[j][1] - nm0);
            sacc[j][2] = __expf(sacc[j][2] - nm1);
            sacc[j][3] = __expf(sacc[j][3] - nm1);
            sum0 += sacc[j][0] + sacc[j][1];
            sum1 += sacc[j][2] + sacc[j][3];
        }
        sum0 += __shfl_xor_sync(0xffffffff, sum0, 1);
        sum0 += __shfl_xor_sync(0xffffffff, sum0, 2);
        sum1 += __shfl_xor_sync(0xffffffff, sum1, 1);
        sum1 += __shfl_xor_sync(0xffffffff, sum1, 2);
        l0 = l0 * sc0 + sum0;
        l1 = l1 * sc1 + sum1;
        m0 = nm0;
        m1 = nm1;
#pragma unroll
        for (int n = 0; n < 8; n++) {
            oacc[n][0] *= sc0;
            oacc[n][1] *= sc0;
            oacc[n][2] *= sc1;
            oacc[n][3] *= sc1;
        }

        // ---- P -> bf16 hi/lo A-operand fragments (direct from registers) ----
        uint32_t pH[32], pL[32];
#pragma unroll
        for (int s = 0; s < 8; s++) {
            cvt_pack(sacc[2 * s][0],     sacc[2 * s][1],     pH[s * 4 + 0], pL[s * 4 + 0]);
            cvt_pack(sacc[2 * s][2],     sacc[2 * s][3],     pH[s * 4 + 1], pL[s * 4 + 1]);
            cvt_pack(sacc[2 * s + 1][0], sacc[2 * s + 1][1], pH[s * 4 + 2], pL[s * 4 + 2]);
            cvt_pack(sacc[2 * s + 1][2], sacc[2 * s + 1][3], pH[s * 4 + 3], pL[s * 4 + 3]);
        }

        // ---- O += P @ V^T : m=16 rows, n=64 d, contract q=128 ----
#pragma unroll
        for (int pass = 0; pass < 3; pass++) {
            const uint32_t* P  = (pass == 1) ? pL : pH;
            const uint32_t sV  = (pass == 2) ? sVsL : sVsH;
#pragma unroll
            for (int s = 0; s < 8; s++) {
#pragma unroll
                for (int j = 0; j < 2; j++) {
                    uint32_t r0, r1, r2, r3;
                    ldsm_x4_t(sV + ((s * 16 + b_k) * KPAD + j * 32 + b_n) * 2,
                              r0, r1, r2, r3);
                    uint32_t bb0[2] = {r0, r1};
                    uint32_t bb1[2] = {r2, r3};
                    mma_bf16(oacc[j * 4 + 0], &P[s * 4], bb0);
                    mma_bf16(oacc[j * 4 + 1], &P[s * 4], bb1);
                    uint32_t r4, r5, r6, r7;
                    ldsm_x4_t(sV + ((s * 16 + b_k) * KPAD + j * 32 + 16 + b_n) * 2,
                              r4, r5, r6, r7);
                    uint32_t bb2[2] = {r4, r5};
                    uint32_t bb3[2] = {r6, r7};
                    mma_bf16(oacc[j * 4 + 2], &P[s * 4], bb2);
                    mma_bf16(oacc[j * 4 + 3], &P[s * 4], bb3);
                }
            }
        }
    }

    // ---- epilogue: normalize, transpose through smem, store g_O[d][k] ----
    const float inv0 = 0.03125f / l0;     // E^-0.5 folded
    const float inv1 = 0.03125f / l1;
    __syncthreads();
    float* Osm = reinterpret_cast<float*>(sm);   // [64 d][OSM_STRIDE]
    {
        const int r0 = wid * 16 + gid;
        const int r1 = r0 + 8;
#pragma unroll
        for (int n = 0; n < 8; n++) {
            int d0 = n * 8 + tid4 * 2;
            Osm[(d0 + 0) * OSM_STRIDE + r0] = oacc[n][0] * inv0;
            Osm[(d0 + 1) * OSM_STRIDE + r0] = oacc[n][1] * inv0;
            Osm[(d0 + 0) * OSM_STRIDE + r1] = oacc[n][2] * inv1;
            Osm[(d0 + 1) * OSM_STRIDE + r1] = oacc[n][3] * inv1;
        }
    }
    __syncthreads();
    {
        const int d  = t >> 2;            // 0..63
        const int kq = t & 3;
#pragma unroll
        for (int i = 0; i < 8; i++) {
            int k = (kq * 8 + i) * 4;
            float4 v = *reinterpret_cast<const float4*>(&Osm[d * OSM_STRIDE + k]);
            *reinterpret_cast<float4*>(&Ob[(size_t)d * W + k0 + k]) = v;
        }
    }
}

// ---------------------------------------------------------------------------
// Launch
// ---------------------------------------------------------------------------
extern "C" void kernel_launch(void* const* d_in, const int* in_sizes, int n_in,
                              void* d_out, int out_size)
{
    const float* x  = (const float*)d_in[0];
    const float* LQ = (const float*)d_in[1];
    const float* LK = (const float*)d_in[2];
    const float* LV = (const float*)d_in[3];
    const float* DM = (const float*)d_in[4];
    const float* Db = (const float*)d_in[5];
    float* out = (float*)d_out;

    float *pQ, *pK, *pV, *pO;
    cudaGetSymbolAddress((void**)&pQ, g_Q);
    cudaGetSymbolAddress((void**)&pK, g_K);
    cudaGetSymbolAddress((void**)&pV, g_V);
    cudaGetSymbolAddress((void**)&pO, g_O);

    cudaFuncSetAttribute(flash_kernel, cudaFuncAttributeMaxDynamicSharedMemorySize, F_TOTAL);

    const size_t BEW = (size_t)BATCH * E * W;

    dim3 gProj(W / 128, E / 128, BATCH);
    gemm_tc<<<gProj, 256>>>(LK, x + 0 * BEW, pK, nullptr);
    gemm_tc<<<gProj, 256>>>(LQ, x + 1 * BEW, pQ, nullptr);
    gemm_tc<<<gProj, 256>>>(LV, x + 2 * BEW, pV, nullptr);

    dim3 gFl(W / 128, BATCH * HEADS);
    flash_kernel<<<gFl, 256, F_TOTAL>>>(pK, pQ, pV, pO);

    gemm_tc<<<gProj, 256>>>(DM, pO, out, Db);
}